// round 1
// baseline (speedup 1.0000x reference)
#include <cuda_runtime.h>
#include <cuda_bf16.h>

// Problem constants
#define BB 16
#define CC 64
#define HH 256
#define WW 256
#define GG 8
#define GS 8

// Tiles
#define TW 32
#define TH 8
#define HALO_W (TW + 2)   // 34
#define HALO_H (TH + 2)   // 10
#define XTILE (HALO_W * HALO_H)      // 340 floats per channel
#define XS_FLOATS (CC * XTILE)       // 21760 floats = 87040 B

// K1: 8-cin weight chunk, 32 couts per block: ws[8][9][32] = 2304 floats
#define CIN_CHUNK 8
#define COUT_BLK 32
#define WS_FLOATS (CIN_CHUNK * 9 * COUT_BLK)

// 256 MB intermediate x_conv buffer (bss, not an allocation)
__device__ float g_xconv[(size_t)BB * CC * HH * WW];

// ---------------------------------------------------------------------------
// Kernel 1: x_conv = conv3x3(x, w, SAME) + conv_b   (each block: 32 couts)
// ---------------------------------------------------------------------------
extern "C" __global__ void __launch_bounds__(256, 2)
k1_conv(const float* __restrict__ x,
        const float* __restrict__ w,
        const float* __restrict__ cb)
{
    extern __shared__ float smem[];
    float* xs = smem;               // [64][10][34]
    float* ws = smem + XS_FLOATS;   // [8][9][32]

    const int tid = threadIdx.x;
    const int b      = blockIdx.z >> 1;
    const int cobase = (blockIdx.z & 1) * COUT_BLK;
    const int h0 = blockIdx.y * TH;
    const int w0 = blockIdx.x * TW;

    // Stage input tile (all 64 cin, with zero halo). 21760/256 = 85 per thread.
    const float* xb = x + (size_t)b * CC * HH * WW;
    for (int i = tid; i < XS_FLOATS; i += 256) {
        int ci  = i / XTILE;
        int r   = i - ci * XTILE;
        int row = r / HALO_W;
        int col = r - row * HALO_W;
        int gh = h0 + row - 1;
        int gw = w0 + col - 1;
        float v = 0.f;
        if ((unsigned)gh < (unsigned)HH && (unsigned)gw < (unsigned)WW)
            v = xb[(size_t)ci * HH * WW + gh * WW + gw];
        xs[i] = v;
    }

    const int lx = tid & 31;
    const int ly = tid >> 5;

    float acc[COUT_BLK];
#pragma unroll
    for (int q = 0; q < COUT_BLK; q++) acc[q] = 0.f;

    for (int cc = 0; cc < CC; cc += CIN_CHUNK) {
        __syncthreads();   // covers xs staging (first iter) and ws reuse
        // Stage transposed weights ws[ci][tap][co] = w[cobase+co][cc+ci][tap]
        for (int i = tid; i < WS_FLOATS; i += 256) {
            int ci  = i / (9 * COUT_BLK);
            int r   = i - ci * (9 * COUT_BLK);
            int tap = r >> 5;
            int co  = r & 31;
            ws[i] = w[(size_t)(cobase + co) * (CC * 9) + (cc + ci) * 9 + tap];
        }
        __syncthreads();

#pragma unroll 2
        for (int ci = 0; ci < CIN_CHUNK; ci++) {
            const float* xc = xs + (cc + ci) * XTILE;
            float xv[9];
#pragma unroll
            for (int t = 0; t < 9; t++) {
                int dy = t / 3, dx = t - 3 * (t / 3);
                xv[t] = xc[(ly + dy) * HALO_W + (lx + dx)];
            }
            const float4* wrow = (const float4*)(ws + ci * (9 * COUT_BLK));
#pragma unroll
            for (int t = 0; t < 9; t++) {
                float xt = xv[t];
#pragma unroll
                for (int q = 0; q < COUT_BLK / 4; q++) {
                    float4 wv = wrow[t * (COUT_BLK / 4) + q];
                    acc[q * 4 + 0] = fmaf(wv.x, xt, acc[q * 4 + 0]);
                    acc[q * 4 + 1] = fmaf(wv.y, xt, acc[q * 4 + 1]);
                    acc[q * 4 + 2] = fmaf(wv.z, xt, acc[q * 4 + 2]);
                    acc[q * 4 + 3] = fmaf(wv.w, xt, acc[q * 4 + 3]);
                }
            }
        }
    }

    const int h = h0 + ly;
    const int wcol = w0 + lx;
    float* outb = g_xconv + (size_t)b * CC * HH * WW;
#pragma unroll
    for (int q = 0; q < COUT_BLK; q++) {
        int c = cobase + q;
        outb[(size_t)c * HH * WW + h * WW + wcol] = acc[q] + cb[c];
    }
}

// ---------------------------------------------------------------------------
// Kernel 2: fused depthwise-diag conv + group stats + gate + residual + LSE
// ---------------------------------------------------------------------------
extern "C" __global__ void __launch_bounds__(256, 2)
k2_fused(const float* __restrict__ w,
         const float* __restrict__ cb,
         const float* __restrict__ gscale,
         const float* __restrict__ gbias,
         float* __restrict__ out)
{
    extern __shared__ float smem[];
    float* xs  = smem;                   // [64][10][34]
    float* wd  = smem + XS_FLOATS;       // [64][9] diag weights
    float* cbs = wd + CC * 9;            // [64]
    float* gss = cbs + CC;               // [64]
    float* gbs = gss + CC;               // [64]

    const int tid = threadIdx.x;
    const int b  = blockIdx.z;
    const int h0 = blockIdx.y * TH;
    const int w0 = blockIdx.x * TW;

    // Stage x_conv tile (zero halo at image borders)
    const float* xb = g_xconv + (size_t)b * CC * HH * WW;
    for (int i = tid; i < XS_FLOATS; i += 256) {
        int ci  = i / XTILE;
        int r   = i - ci * XTILE;
        int row = r / HALO_W;
        int col = r - row * HALO_W;
        int gh = h0 + row - 1;
        int gw = w0 + col - 1;
        float v = 0.f;
        if ((unsigned)gh < (unsigned)HH && (unsigned)gw < (unsigned)WW)
            v = xb[(size_t)ci * HH * WW + gh * WW + gw];
        xs[i] = v;
    }
    // Stage diag weights: wd[c][tap] = w[c][c][tap]
    for (int i = tid; i < CC * 9; i += 256) {
        int c = i / 9, tap = i - 9 * (i / 9);
        wd[i] = w[(size_t)c * (CC * 9) + c * 9 + tap];
    }
    if (tid < CC) {
        cbs[tid] = cb[tid];
        gss[tid] = gscale[tid];
        gbs[tid] = gbias[tid];
    }
    __syncthreads();

    const int lx = tid & 31;
    const int ly = tid >> 5;
    const int center = (ly + 1) * HALO_W + (lx + 1);

    // Upper bound for logsumexp: max_c x_conv + 1  (|fused| <= 1)
    float m = -1e30f;
#pragma unroll
    for (int c = 0; c < CC; c++)
        m = fmaxf(m, xs[c * XTILE + center]);
    m += 1.0f;

    float s = 0.f;
    for (int g = 0; g < GG; g++) {
        float xc[GS];
        float sum = 0.f;
#pragma unroll
        for (int j = 0; j < GS; j++) {
            xc[j] = xs[(g * GS + j) * XTILE + center];
            sum += xc[j];
        }
        float mean = sum * (1.0f / GS);
        float vs = 0.f;
#pragma unroll
        for (int j = 0; j < GS; j++) {
            float d = xc[j] - mean;
            vs = fmaf(d, d, vs);
        }
        float inv = rsqrtf(vs * (1.0f / GS) + 1e-5f);

#pragma unroll
        for (int j = 0; j < GS; j++) {
            int c = g * GS + j;
            const float* xcp = xs + c * XTILE;
            const float* wdp = wd + c * 9;
            float a = cbs[c];
#pragma unroll
            for (int t = 0; t < 9; t++) {
                int dy = t / 3, dx = t - 3 * (t / 3);
                a = fmaf(wdp[t], xcp[(ly + dy) * HALO_W + (lx + dx)], a);
            }
            float norm = (a - mean) * inv * gss[c] + gbs[c];
            float gate = __saturatef(norm * (1.0f / 6.0f) + 0.5f);
            float e2   = __expf(2.0f * norm);
            float th   = 1.0f - __fdividef(2.0f, e2 + 1.0f);
            float v    = xc[j] + th * gate;
            s += __expf(v - m);
        }
    }

    out[((size_t)b << 16) + (h0 + ly) * WW + (w0 + lx)] = m + __logf(s);
}

// ---------------------------------------------------------------------------
extern "C" void kernel_launch(void* const* d_in, const int* in_sizes, int n_in,
                              void* d_out, int out_size)
{
    const float* x   = (const float*)d_in[0];
    const float* w   = (const float*)d_in[1];
    const float* cb  = (const float*)d_in[2];
    const float* gsc = (const float*)d_in[3];
    const float* gbi = (const float*)d_in[4];
    float* out = (float*)d_out;

    const int smem1 = (XS_FLOATS + WS_FLOATS) * sizeof(float);          // 96256 B
    const int smem2 = (XS_FLOATS + CC * 9 + 3 * CC) * sizeof(float);    // 90112 B
    cudaFuncSetAttribute(k1_conv,  cudaFuncAttributeMaxDynamicSharedMemorySize, smem1);
    cudaFuncSetAttribute(k2_fused, cudaFuncAttributeMaxDynamicSharedMemorySize, smem2);

    dim3 grid1(WW / TW, HH / TH, BB * 2);   // (8, 32, 32)
    k1_conv<<<grid1, 256, smem1>>>(x, w, cb);

    dim3 grid2(WW / TW, HH / TH, BB);       // (8, 32, 16)
    k2_fused<<<grid2, 256, smem2>>>(w, cb, gsc, gbi, out);
}

// round 3
// speedup vs baseline: 1.0918x; 1.0918x over previous
#include <cuda_runtime.h>
#include <cuda_bf16.h>

// Problem constants
#define BB 16
#define CC 64
#define HH 256
#define WW 256
#define GG 8
#define GS 8

// Tiles
#define TW 32
#define TH 8
#define HALO_W (TW + 2)   // 34
#define HALO_H (TH + 2)   // 10
#define XTILE (HALO_W * HALO_H)      // 340 floats per channel
#define XS_FLOATS (CC * XTILE)       // 21760 floats = 87040 B

// K1: 8-cin weight chunk, ALL 64 couts per block: ws[8][9][64] = 4608 floats
#define CIN_CHUNK 8
#define COUT_BLK 64
#define NPAIR (COUT_BLK / 2)          // 32 packed f32x2 accumulators
#define WS_FLOATS (CIN_CHUNK * 9 * COUT_BLK)

// 256 MB intermediate x_conv buffer (bss, not an allocation)
__device__ float g_xconv[(size_t)BB * CC * HH * WW];

// ---------------------------------------------------------------------------
// Kernel 1: x_conv = conv3x3(x, w, SAME) + conv_b
//   - packed f32x2 FFMA2 via PTX (2 MACs per fma-pipe slot)
//   - 64 couts per thread as 32 u64 accumulators
// ---------------------------------------------------------------------------
extern "C" __global__ void __launch_bounds__(256, 2)
k1_conv(const float* __restrict__ x,
        const float* __restrict__ w,
        const float* __restrict__ cb)
{
    extern __shared__ float smem[];
    float* xs = smem;               // [64][10][34]
    float* ws = smem + XS_FLOATS;   // [8][9][64]

    const int tid = threadIdx.x;
    const int b  = blockIdx.z;
    const int h0 = blockIdx.y * TH;
    const int w0 = blockIdx.x * TW;

    // Stage input tile (all 64 cin, with zero halo). 21760/256 = 85 per thread.
    const float* xb = x + (size_t)b * CC * HH * WW;
    for (int i = tid; i < XS_FLOATS; i += 256) {
        int ci  = i / XTILE;
        int r   = i - ci * XTILE;
        int row = r / HALO_W;
        int col = r - row * HALO_W;
        int gh = h0 + row - 1;
        int gw = w0 + col - 1;
        float v = 0.f;
        if ((unsigned)gh < (unsigned)HH && (unsigned)gw < (unsigned)WW)
            v = xb[(size_t)ci * HH * WW + gh * WW + gw];
        xs[i] = v;
    }

    const int lx = tid & 31;
    const int ly = tid >> 5;

    unsigned long long acc[NPAIR];   // packed {co=2q, co=2q+1}
#pragma unroll
    for (int q = 0; q < NPAIR; q++) acc[q] = 0ULL;

    for (int cc = 0; cc < CC; cc += CIN_CHUNK) {
        __syncthreads();   // covers xs staging (first iter) and ws reuse
        // Stage transposed weights ws[ci][tap][co] = w[co][cc+ci][tap]
        for (int i = tid; i < WS_FLOATS; i += 256) {
            int ci  = i / (9 * COUT_BLK);
            int r   = i - ci * (9 * COUT_BLK);
            int tap = r >> 6;
            int co  = r & 63;
            ws[i] = w[(size_t)co * (CC * 9) + (cc + ci) * 9 + tap];
        }
        __syncthreads();

        for (int ci = 0; ci < CIN_CHUNK; ci++) {
            const float* xc = xs + (cc + ci) * XTILE;
            unsigned long long xx[9];
#pragma unroll
            for (int t = 0; t < 9; t++) {
                int dy = t / 3, dx = t - 3 * (t / 3);
                float xt = xc[(ly + dy) * HALO_W + (lx + dx)];
                asm("mov.b64 %0, {%1, %1};" : "=l"(xx[t]) : "f"(xt));
            }
            const ulonglong2* wrow = (const ulonglong2*)(ws + ci * (9 * COUT_BLK));
#pragma unroll
            for (int t = 0; t < 9; t++) {
                unsigned long long xv = xx[t];
#pragma unroll
                for (int q = 0; q < NPAIR / 2; q++) {
                    ulonglong2 wp = wrow[t * (NPAIR / 2) + q];
                    asm("fma.rn.f32x2 %0, %1, %2, %0;"
                        : "+l"(acc[2 * q + 0]) : "l"(wp.x), "l"(xv));
                    asm("fma.rn.f32x2 %0, %1, %2, %0;"
                        : "+l"(acc[2 * q + 1]) : "l"(wp.y), "l"(xv));
                }
            }
        }
    }

    const int h = h0 + ly;
    const int wcol = w0 + lx;
    float* outb = g_xconv + (size_t)b * CC * HH * WW + (size_t)h * WW + wcol;
#pragma unroll
    for (int q = 0; q < NPAIR; q++) {
        float2 f = *(float2*)&acc[q];
        outb[(size_t)(2 * q + 0) * HH * WW] = f.x + cb[2 * q + 0];
        outb[(size_t)(2 * q + 1) * HH * WW] = f.y + cb[2 * q + 1];
    }
}

// ---------------------------------------------------------------------------
// Kernel 2: fused depthwise-diag conv + group stats + gate + residual + LSE
// ---------------------------------------------------------------------------
extern "C" __global__ void __launch_bounds__(256, 2)
k2_fused(const float* __restrict__ w,
         const float* __restrict__ cb,
         const float* __restrict__ gscale,
         const float* __restrict__ gbias,
         float* __restrict__ out)
{
    extern __shared__ float smem[];
    float* xs  = smem;                   // [64][10][34]
    float* wd  = smem + XS_FLOATS;       // [64][9] diag weights
    float* cbs = wd + CC * 9;            // [64]
    float* gss = cbs + CC;               // [64]
    float* gbs = gss + CC;               // [64]

    const int tid = threadIdx.x;
    const int b  = blockIdx.z;
    const int h0 = blockIdx.y * TH;
    const int w0 = blockIdx.x * TW;

    // Stage x_conv tile (zero halo at image borders)
    const float* xb = g_xconv + (size_t)b * CC * HH * WW;
    for (int i = tid; i < XS_FLOATS; i += 256) {
        int ci  = i / XTILE;
        int r   = i - ci * XTILE;
        int row = r / HALO_W;
        int col = r - row * HALO_W;
        int gh = h0 + row - 1;
        int gw = w0 + col - 1;
        float v = 0.f;
        if ((unsigned)gh < (unsigned)HH && (unsigned)gw < (unsigned)WW)
            v = xb[(size_t)ci * HH * WW + gh * WW + gw];
        xs[i] = v;
    }
    // Stage diag weights: wd[c][tap] = w[c][c][tap]
    for (int i = tid; i < CC * 9; i += 256) {
        int c = i / 9, tap = i - 9 * (i / 9);
        wd[i] = w[(size_t)c * (CC * 9) + c * 9 + tap];
    }
    if (tid < CC) {
        cbs[tid] = cb[tid];
        gss[tid] = gscale[tid];
        gbs[tid] = gbias[tid];
    }
    __syncthreads();

    const int lx = tid & 31;
    const int ly = tid >> 5;
    const int center = (ly + 1) * HALO_W + (lx + 1);

    // Upper bound for logsumexp: max_c x_conv + 1  (|fused| <= 1)
    float m = -1e30f;
#pragma unroll
    for (int c = 0; c < CC; c++)
        m = fmaxf(m, xs[c * XTILE + center]);
    m += 1.0f;

    float s = 0.f;
    for (int g = 0; g < GG; g++) {
        float xc[GS];
        float sum = 0.f;
#pragma unroll
        for (int j = 0; j < GS; j++) {
            xc[j] = xs[(g * GS + j) * XTILE + center];
            sum += xc[j];
        }
        float mean = sum * (1.0f / GS);
        float vs = 0.f;
#pragma unroll
        for (int j = 0; j < GS; j++) {
            float d = xc[j] - mean;
            vs = fmaf(d, d, vs);
        }
        float inv = rsqrtf(vs * (1.0f / GS) + 1e-5f);

#pragma unroll
        for (int j = 0; j < GS; j++) {
            int c = g * GS + j;
            const float* xcp = xs + c * XTILE;
            const float* wdp = wd + c * 9;
            float a = cbs[c];
#pragma unroll
            for (int t = 0; t < 9; t++) {
                int dy = t / 3, dx = t - 3 * (t / 3);
                a = fmaf(wdp[t], xcp[(ly + dy) * HALO_W + (lx + dx)], a);
            }
            float norm = (a - mean) * inv * gss[c] + gbs[c];
            float gate = __saturatef(norm * (1.0f / 6.0f) + 0.5f);
            float e2   = __expf(2.0f * norm);
            float th   = 1.0f - __fdividef(2.0f, e2 + 1.0f);
            float v    = xc[j] + th * gate;
            s += __expf(v - m);
        }
    }

    out[((size_t)b << 16) + (h0 + ly) * WW + (w0 + lx)] = m + __logf(s);
}

// ---------------------------------------------------------------------------
extern "C" void kernel_launch(void* const* d_in, const int* in_sizes, int n_in,
                              void* d_out, int out_size)
{
    const float* x   = (const float*)d_in[0];
    const float* w   = (const float*)d_in[1];
    const float* cb  = (const float*)d_in[2];
    const float* gsc = (const float*)d_in[3];
    const float* gbi = (const float*)d_in[4];
    float* out = (float*)d_out;

    const int smem1 = (XS_FLOATS + WS_FLOATS) * sizeof(float);          // 105472 B
    const int smem2 = (XS_FLOATS + CC * 9 + 3 * CC) * sizeof(float);    // 90112 B
    cudaFuncSetAttribute(k1_conv,  cudaFuncAttributeMaxDynamicSharedMemorySize, smem1);
    cudaFuncSetAttribute(k2_fused, cudaFuncAttributeMaxDynamicSharedMemorySize, smem2);

    dim3 grid1(WW / TW, HH / TH, BB);       // (8, 32, 16)
    k1_conv<<<grid1, 256, smem1>>>(x, w, cb);

    dim3 grid2(WW / TW, HH / TH, BB);       // (8, 32, 16)
    k2_fused<<<grid2, 256, smem2>>>(w, cb, gsc, gbi, out);
}

// round 5
// speedup vs baseline: 2.9106x; 2.6658x over previous
#include <cuda_runtime.h>
#include <cuda_bf16.h>
#include <cstdint>

// Problem constants
#define BB 16
#define CC 64
#define HH 256
#define WW 256
#define GG 8
#define GS 8

// ---------------- k1 tiling ----------------
// CTA tile: M=256 pixels (2 rows x 128 cols) x N=64 couts, K = 9 taps x 64 cin.
// A smem: 4 image rows x 130 halo pixels, each pixel-row = 64 ci bf16 = 128B (swizzled).
// B smem: 2 terms x 9 taps x [64 co][64 ci] bf16 (swizzled), staged once.
// Epilogue reuses the A region as a fp32 [256][68] transpose buffer.
#define EPI_PAD 68
#define EPI_BYTES (256 * EPI_PAD * 4)      // 69632 (>= A raw 66560)
#define B_OFF EPI_BYTES
#define B_TERM_BYTES 73728                  // 9*64*64*2
#define B_BYTES (2 * B_TERM_BYTES)          // 147456
#define SMEM1 (B_OFF + B_BYTES)             // 217088

// Big device buffers (bss, not allocations)
__device__ float         g_xconv[(size_t)BB * HH * WW * CC];   // [b][h][w][c]
__device__ __align__(16) __nv_bfloat16 g_xth[(size_t)BB * HH * WW * CC]; // hi, [b][h][w][c]
__device__ __align__(16) __nv_bfloat16 g_xtl[(size_t)BB * HH * WW * CC]; // lo
__device__ __align__(16) __nv_bfloat16 g_wsw[2][9][CC * CC];   // [term][tap][co][ci] swizzled

__device__ __forceinline__ uint32_t smem_u32(const void* p) {
    uint32_t a;
    asm("{ .reg .u64 t; cvta.to.shared.u64 t, %1; cvt.u32.u64 %0, t; }" : "=r"(a) : "l"(p));
    return a;
}
__device__ __forceinline__ void ldsm4(uint32_t* r, uint32_t addr) {
    asm volatile("ldmatrix.sync.aligned.m8n8.x4.shared.b16 {%0,%1,%2,%3}, [%4];"
                 : "=r"(r[0]), "=r"(r[1]), "=r"(r[2]), "=r"(r[3]) : "r"(addr));
}
__device__ __forceinline__ void hmma(float* c, const uint32_t* a, const uint32_t* b) {
    asm volatile(
        "mma.sync.aligned.m16n8k16.row.col.f32.bf16.bf16.f32 "
        "{%0,%1,%2,%3}, {%4,%5,%6,%7}, {%8,%9}, {%0,%1,%2,%3};"
        : "+f"(c[0]), "+f"(c[1]), "+f"(c[2]), "+f"(c[3])
        : "r"(a[0]), "r"(a[1]), "r"(a[2]), "r"(a[3]), "r"(b[0]), "r"(b[1]));
}

// ---------------------------------------------------------------------------
// k0w: weights -> bf16 hi/lo, layout [term][tap][co][ci] with 16B-chunk swizzle
// ---------------------------------------------------------------------------
extern "C" __global__ void k0_wconv(const float* __restrict__ w)
{
    int tap = blockIdx.x;     // 0..8
    int term = blockIdx.y;    // 0 hi, 1 lo
    for (int i = threadIdx.x; i < CC * CC; i += 256) {
        int co = i >> 6, ci = i & 63;
        float v = w[(size_t)(co * CC + ci) * 9 + tap];
        __nv_bfloat16 hi = __float2bfloat16(v);
        __nv_bfloat16 o = (term == 0) ? hi : __float2bfloat16(v - __bfloat162float(hi));
        uint32_t byte = (uint32_t)co * 128 + ((((uint32_t)ci >> 3) ^ ((uint32_t)co & 7)) << 4)
                      + ((uint32_t)ci & 7) * 2;
        g_wsw[term][tap][byte >> 1] = o;
    }
}

// ---------------------------------------------------------------------------
// k0x: transpose x [b][c][h][w] f32 -> [b][h][w][c] bf16 hi and lo
//   one CTA per (b,h) row: 64 c x 256 w
// ---------------------------------------------------------------------------
extern "C" __global__ void __launch_bounds__(256, 1)
k0_xconv(const float* __restrict__ x)
{
    extern __shared__ uint32_t shp[];   // [256 pix][68] packed {hi, lo<<16}
    const int tid = threadIdx.x;
    const int b = blockIdx.x >> 8;
    const int h = blockIdx.x & 255;
    const float* xr = x + ((size_t)b * CC * HH + h) * WW;   // + c*HH*WW + w

    for (int c = 0; c < CC; c++) {
        float v = xr[(size_t)c * HH * WW + tid];
        __nv_bfloat16 hi = __float2bfloat16(v);
        __nv_bfloat16 lo = __float2bfloat16(v - __bfloat162float(hi));
        uint32_t p = (uint32_t)__bfloat16_as_ushort(hi)
                   | ((uint32_t)__bfloat16_as_ushort(lo) << 16);
        shp[tid * EPI_PAD + c] = p;
    }
    __syncthreads();

    __nv_bfloat16* oh = g_xth + (((size_t)b * HH + h) * WW) * CC;
    __nv_bfloat16* ol = g_xtl + (((size_t)b * HH + h) * WW) * CC;
    // 256 pix x 16 chunks of 4 c
    for (int i = tid; i < 256 * 16; i += 256) {
        int pix = i >> 4, k4 = i & 15;
        uint4 q = *(const uint4*)&shp[pix * EPI_PAD + k4 * 4];
        uint2 hv, lv;
        hv.x = (q.x & 0xFFFFu) | (q.y << 16);
        hv.y = (q.z & 0xFFFFu) | (q.w << 16);
        lv.x = (q.x >> 16) | (q.y & 0xFFFF0000u);
        lv.y = (q.z >> 16) | (q.w & 0xFFFF0000u);
        *(uint2*)(oh + (size_t)pix * CC + k4 * 4) = hv;
        *(uint2*)(ol + (size_t)pix * CC + k4 * 4) = lv;
    }
}

// ---------------------------------------------------------------------------
// k1: conv3x3 + bias via mma.sync bf16 (3-term split), out [b][h][w][c]
//   grid (2, 128, 16) = (w-half, h-pair, b); 256 threads (8 warps)
// ---------------------------------------------------------------------------
extern "C" __global__ void __launch_bounds__(256, 1)
k1_conv(const float* __restrict__ cb)
{
    extern __shared__ char smem[];
    const uint32_t sA = smem_u32(smem);
    const uint32_t sB = sA + B_OFF;
    const int tid = threadIdx.x;
    const int wid = tid >> 5;
    const int lid = tid & 31;

    const int b  = blockIdx.z;
    const int h0 = blockIdx.y * 2;
    const int w0 = blockIdx.x * 128;

    // ---- stage B (both terms, once): 9216 uint4 from pre-swizzled g_wsw ----
    {
        const uint4* src = (const uint4*)&g_wsw[0][0][0];
        uint4* dst = (uint4*)(smem + B_OFF);
        for (int i = tid; i < B_BYTES / 16; i += 256) dst[i] = src[i];
    }

    // ldmatrix lane constants
    const int am  = lid & 15;            // A: pixel offset within m16
    const int akh = (lid >> 4) & 1;      // A: k-half (8 ci)
    const int bco = (lid & 7) + ((lid >= 16) ? 8 : 0);  // B: co within n16
    const int bkh = (lid >> 3) & 1;      // B: k-half
    const int pbase = wid * 16;

    float c[2][8][4];
#pragma unroll
    for (int hh = 0; hh < 2; hh++)
#pragma unroll
        for (int nb = 0; nb < 8; nb++)
#pragma unroll
            for (int q = 0; q < 4; q++) c[hh][nb][q] = 0.f;

    for (int aterm = 0; aterm < 2; aterm++) {
        __syncthreads();   // B staged (first pass) / previous MMA phase done
        // ---- stage A: 4 image rows (h0-1..h0+2) x 130 halo px x 64 ci bf16 ----
        const __nv_bfloat16* xt = aterm ? g_xtl : g_xth;
        for (int i = tid; i < 4 * 130 * 8; i += 256) {
            int rs = i >> 3, chunk = i & 7;
            int R  = rs / 130;
            int px = rs - R * 130;
            int gh = h0 - 1 + R;
            int gw = w0 - 1 + px;
            uint4 v = make_uint4(0, 0, 0, 0);
            if ((unsigned)gh < (unsigned)HH && (unsigned)gw < (unsigned)WW)
                v = *(const uint4*)(xt + ((((size_t)b * HH + gh) * WW + gw) * CC) + chunk * 8);
            *(uint4*)(smem + rs * 128 + ((chunk ^ (rs & 7)) << 4)) = v;
        }
        __syncthreads();

        const int nbt = 2 - aterm;   // xh pairs with {wh, wl}; xl with {wh}
        for (int tap = 0; tap < 9; tap++) {
            const int dy = tap / 3, dx = tap - 3 * (tap / 3);
            const uint32_t btap = sB + tap * 8192 + bco * 128;
#pragma unroll
            for (int kb = 0; kb < 4; kb++) {
                uint32_t a[2][4];
#pragma unroll
                for (int hh = 0; hh < 2; hh++) {
                    int rs = (hh + dy) * 130 + pbase + dx + am;
                    uint32_t addr = sA + rs * 128
                                  + ((((uint32_t)(kb * 2 + akh)) ^ (rs & 7)) << 4);
                    ldsm4(a[hh], addr);
                }
                for (int bt = 0; bt < nbt; bt++) {
                    uint32_t bb[4][4];
#pragma unroll
                    for (int j = 0; j < 4; j++) {
                        uint32_t co = (uint32_t)(j * 16 + bco);
                        uint32_t addr = btap + bt * B_TERM_BYTES + j * 16 * 128
                                      + ((((uint32_t)(kb * 2 + bkh)) ^ (co & 7)) << 4);
                        ldsm4(bb[j], addr);
                    }
#pragma unroll
                    for (int hh = 0; hh < 2; hh++)
#pragma unroll
                        for (int j = 0; j < 4; j++) {
                            hmma(c[hh][2 * j + 0], a[hh], &bb[j][0]);
                            hmma(c[hh][2 * j + 1], a[hh], &bb[j][2]);
                        }
                }
            }
        }
    }

    // ---- epilogue: C frags -> smem [256 px][68] f32 -> coalesced gmem ----
    __syncthreads();
    float* smf = (float*)smem;
    const int mrow = (lid >> 2);         // l/4
    const int qcol = (lid & 3) * 2;
#pragma unroll
    for (int hh = 0; hh < 2; hh++)
#pragma unroll
        for (int nb = 0; nb < 8; nb++) {
            int m0 = hh * 128 + pbase + mrow;
            int co = nb * 8 + qcol;
            *(float2*)&smf[m0 * EPI_PAD + co]       = make_float2(c[hh][nb][0], c[hh][nb][1]);
            *(float2*)&smf[(m0 + 8) * EPI_PAD + co] = make_float2(c[hh][nb][2], c[hh][nb][3]);
        }
    __syncthreads();

    for (int i = tid; i < 256 * 16; i += 256) {
        int pix = i >> 4, k4 = i & 15;
        float4 v = *(float4*)&smf[pix * EPI_PAD + k4 * 4];
        int cc4 = k4 * 4;
        v.x += __ldg(cb + cc4 + 0);
        v.y += __ldg(cb + cc4 + 1);
        v.z += __ldg(cb + cc4 + 2);
        v.w += __ldg(cb + cc4 + 3);
        int gh = h0 + (pix >> 7);
        int gw = w0 + (pix & 127);
        *(float4*)(g_xconv + (((size_t)b * HH + gh) * WW + gw) * CC + cc4) = v;
    }
}

// ---------------------------------------------------------------------------
// k2: fused depthwise-diag conv + group stats + gate + residual + LSE
//   (reads x_conv in [b][h][w][c] layout -> coalesced staging)
// ---------------------------------------------------------------------------
#define TW 32
#define TH 8
#define HALO_W (TW + 2)
#define HALO_H (TH + 2)
#define XTILE (HALO_W * HALO_H)
#define XS_FLOATS (CC * XTILE)

extern "C" __global__ void __launch_bounds__(256, 2)
k2_fused(const float* __restrict__ w,
         const float* __restrict__ cb,
         const float* __restrict__ gscale,
         const float* __restrict__ gbias,
         float* __restrict__ out)
{
    extern __shared__ float smemf[];
    float* xs  = smemf;
    float* wd  = smemf + XS_FLOATS;
    float* cbs = wd + CC * 9;
    float* gss = cbs + CC;
    float* gbs = gss + CC;

    const int tid = threadIdx.x;
    const int b  = blockIdx.z;
    const int h0 = blockIdx.y * TH;
    const int w0 = blockIdx.x * TW;

    const float* xb = g_xconv + (size_t)b * HH * WW * CC;
    // stage: i -> (pixel, ci) with ci fastest => coalesced 256B reads per pixel
    for (int i = tid; i < XTILE * CC; i += 256) {
        int pix = i >> 6;            // 0..339
        int ci  = i & 63;
        int row = pix / HALO_W;
        int col = pix - row * HALO_W;
        int gh = h0 + row - 1;
        int gw = w0 + col - 1;
        float v = 0.f;
        if ((unsigned)gh < (unsigned)HH && (unsigned)gw < (unsigned)WW)
            v = xb[((size_t)gh * WW + gw) * CC + ci];
        xs[ci * XTILE + pix] = v;
    }
    for (int i = tid; i < CC * 9; i += 256) {
        int cch = i / 9, tap = i - 9 * (i / 9);
        wd[i] = w[(size_t)cch * (CC * 9) + cch * 9 + tap];
    }
    if (tid < CC) {
        cbs[tid] = cb[tid];
        gss[tid] = gscale[tid];
        gbs[tid] = gbias[tid];
    }
    __syncthreads();

    const int lx = tid & 31;
    const int ly = tid >> 5;
    const int center = (ly + 1) * HALO_W + (lx + 1);

    float m = -1e30f;
#pragma unroll
    for (int cch = 0; cch < CC; cch++)
        m = fmaxf(m, xs[cch * XTILE + center]);
    m += 1.0f;

    float s = 0.f;
    for (int g = 0; g < GG; g++) {
        float xc[GS];
        float sum = 0.f;
#pragma unroll
        for (int j = 0; j < GS; j++) {
            xc[j] = xs[(g * GS + j) * XTILE + center];
            sum += xc[j];
        }
        float mean = sum * (1.0f / GS);
        float vs = 0.f;
#pragma unroll
        for (int j = 0; j < GS; j++) {
            float dd = xc[j] - mean;
            vs = fmaf(dd, dd, vs);
        }
        float inv = rsqrtf(vs * (1.0f / GS) + 1e-5f);

#pragma unroll
        for (int j = 0; j < GS; j++) {
            int cch = g * GS + j;
            const float* xcp = xs + cch * XTILE;
            const float* wdp = wd + cch * 9;
            float a = cbs[cch];
#pragma unroll
            for (int t = 0; t < 9; t++) {
                int dy = t / 3, dx = t - 3 * (t / 3);
                a = fmaf(wdp[t], xcp[(ly + dy) * HALO_W + (lx + dx)], a);
            }
            float norm = (a - mean) * inv * gss[cch] + gbs[cch];
            float gate = __saturatef(norm * (1.0f / 6.0f) + 0.5f);
            float e2   = __expf(2.0f * norm);
            float th   = 1.0f - __fdividef(2.0f, e2 + 1.0f);
            float v    = xc[j] + th * gate;
            s += __expf(v - m);
        }
    }

    out[((size_t)b << 16) + (h0 + ly) * WW + (w0 + lx)] = m + __logf(s);
}

// ---------------------------------------------------------------------------
extern "C" void kernel_launch(void* const* d_in, const int* in_sizes, int n_in,
                              void* d_out, int out_size)
{
    const float* x   = (const float*)d_in[0];
    const float* w   = (const float*)d_in[1];
    const float* cb  = (const float*)d_in[2];
    const float* gsc = (const float*)d_in[3];
    const float* gbi = (const float*)d_in[4];
    float* out = (float*)d_out;

    cudaFuncSetAttribute(k0_xconv, cudaFuncAttributeMaxDynamicSharedMemorySize, EPI_BYTES);
    cudaFuncSetAttribute(k1_conv,  cudaFuncAttributeMaxDynamicSharedMemorySize, SMEM1);
    const int smem2 = (XS_FLOATS + CC * 9 + 3 * CC) * sizeof(float);
    cudaFuncSetAttribute(k2_fused, cudaFuncAttributeMaxDynamicSharedMemorySize, smem2);

    k0_wconv<<<dim3(9, 2), 256>>>(w);
    k0_xconv<<<BB * HH, 256, EPI_BYTES>>>(x);

    dim3 grid1(2, 128, BB);
    k1_conv<<<grid1, 256, SMEM1>>>(cb);

    dim3 grid2(WW / TW, HH / TH, BB);
    k2_fused<<<grid2, 256, smem2>>>(w, cb, gsc, gbi, out);
}